// round 2
// baseline (speedup 1.0000x reference)
#include <cuda_runtime.h>
#include <math.h>

#define BATCH   128
#define TSTEPS  256
#define HORIZON 512
#define OBS     32
#define LAT     256
#define HID     1024
#define NB      148     // persistent grid (<= SM count, guarantees co-residency)
#define NT      256     // persistent block size

// ---------------------------------------------------------------------------
// Scratch (device globals)
// ---------------------------------------------------------------------------
__device__ float g_Z[(size_t)(HORIZON + 1) * BATCH * LAT];   // z_0 .. z_511
__device__ float g_A[(size_t)64 * BATCH * HID];
__device__ float g_B[(size_t)64 * BATCH * HID];
__device__ unsigned g_bar;                                   // grid barrier counter

// ---------------------------------------------------------------------------
// Software grid barrier (epoch-based; g_bar memset to 0 before each kernel)
// ---------------------------------------------------------------------------
__device__ __forceinline__ void grid_sync(unsigned& epoch) {
    epoch++;
    __syncthreads();
    if (threadIdx.x == 0) {
        __threadfence();
        atomicAdd(&g_bar, 1u);
        const unsigned goal = epoch * gridDim.x;
        while (*((volatile unsigned*)&g_bar) < goal) { __nanosleep(64); }
        __threadfence();
    }
    __syncthreads();
}

// ---------------------------------------------------------------------------
// Phase 1a: teacher-forced recurrence, one persistent kernel.
// CTA b (< 128) owns batch row b; thread n = tid computes z_{t+1}[b][n].
// z row in smem; W_hh rows stream via __ldg (L1-resident across steps).
// ---------------------------------------------------------------------------
__global__ void __launch_bounds__(NT) phase1a_kernel(
    const float* __restrict__ y,
    const float* __restrict__ Wih, const float* __restrict__ Whh,
    const float* __restrict__ bih, const float* __restrict__ bhh,
    float* __restrict__ Z)
{
    unsigned epoch = 0;
    const int tid = threadIdx.x;
    const int b   = blockIdx.x;
    __shared__ float sz[LAT];
    __shared__ float sy[OBS];

    // z_0 = 0
    for (int i = blockIdx.x * NT + tid; i < BATCH * LAT; i += NB * NT)
        __stcg(&Z[i], 0.0f);
    grid_sync(epoch);

    float bsum = 0.0f;
    if (b < BATCH) bsum = __ldg(bih + tid) + __ldg(bhh + tid);

    for (int t = 0; t < TSTEPS; t++) {
        if (b < BATCH) {
            sz[tid] = __ldcg(Z + (size_t)t * BATCH * LAT + b * LAT + tid);
            if (tid < OBS)
                sy[tid] = __ldg(y + ((size_t)b * TSTEPS + t) * OBS + tid);
        }
        __syncthreads();
        if (b < BATCH) {
            const int n = tid;
            float acc = bsum;
            const float4* wi = (const float4*)(Wih + (size_t)n * OBS);
#pragma unroll
            for (int k4 = 0; k4 < OBS / 4; k4++) {
                float4 w = __ldg(wi + k4);
                acc += sy[k4*4+0]*w.x + sy[k4*4+1]*w.y + sy[k4*4+2]*w.z + sy[k4*4+3]*w.w;
            }
            const float4* wh = (const float4*)(Whh + (size_t)n * LAT);
#pragma unroll 8
            for (int k4 = 0; k4 < LAT / 4; k4++) {
                float4 w = __ldg(wh + k4);
                acc += sz[k4*4+0]*w.x + sz[k4*4+1]*w.y + sz[k4*4+2]*w.z + sz[k4*4+3]*w.w;
            }
            __stcg(Z + (size_t)(t + 1) * BATCH * LAT + b * LAT + n, tanhf(acc));
        }
        grid_sync(epoch);
    }
}

// ---------------------------------------------------------------------------
// Phase-2 building block: one 16 x TN tile, one K-chunk of 32.
// X tile via __ldcg (activations), W tile via __ldg (weights).
// ---------------------------------------------------------------------------
template<int TN>
__device__ __forceinline__ void gemm_chunk(
    const float* __restrict__ X, int ldx,      // X + mB*ldx + k0
    const float* __restrict__ W, int ldw,      // W + nB*ldw + k0
    float* sX, float* sW, float (&acc)[TN / 16])
{
    const int tid = threadIdx.x;
    constexpr int SW = TN + 4;
    if (tid < 128) {
        int row = tid >> 3, c4 = tid & 7;
        float4 v = __ldcg((const float4*)(X + (size_t)row * ldx) + c4);
        sX[(c4*4+0)*17 + row] = v.x; sX[(c4*4+1)*17 + row] = v.y;
        sX[(c4*4+2)*17 + row] = v.z; sX[(c4*4+3)*17 + row] = v.w;
    }
#pragma unroll
    for (int i = tid; i < TN * 8; i += NT) {
        int row = i >> 3, c4 = i & 7;
        float4 v = __ldg((const float4*)(W + (size_t)row * ldw) + c4);
        sW[(c4*4+0)*SW + row] = v.x; sW[(c4*4+1)*SW + row] = v.y;
        sW[(c4*4+2)*SW + row] = v.z; sW[(c4*4+3)*SW + row] = v.w;
    }
    __syncthreads();
    const int ty = tid >> 4, tx = tid & 15;
    constexpr int RN = TN / 16;
#pragma unroll
    for (int kk = 0; kk < 32; kk++) {
        float a = sX[kk * 17 + ty];
        if constexpr (RN == 4) {
            float4 w = *(const float4*)(sW + kk * SW + tx * 4);
            acc[0] += a * w.x; acc[1] += a * w.y; acc[2] += a * w.z; acc[3] += a * w.w;
        } else {
            float2 w = *(const float2*)(sW + kk * SW + tx * 2);
            acc[0] += a * w.x; acc[1] += a * w.y;
        }
    }
    __syncthreads();
}

// Y[128, N] = act( X[128, K] @ W[N, K]^T + bias );  tile-stride over CTAs.
template<int ACT, int TN>   // ACT: 0 none, 1 relu
__device__ __forceinline__ void dense128(
    const float* __restrict__ X, int ldx, int K,
    const float* __restrict__ W, int ldw,
    const float* __restrict__ bias,
    float* __restrict__ Y, int ldy, int N,
    float* sX, float* sW)
{
    const int tid = threadIdx.x, ty = tid >> 4, tx = tid & 15;
    const int colTiles = N / TN;
    constexpr int RN = TN / 16;
    for (int tile = blockIdx.x; tile < 8 * colTiles; tile += gridDim.x) {
        const int mB = (tile / colTiles) * 16;
        const int nB = (tile % colTiles) * TN;
        float acc[RN];
#pragma unroll
        for (int j = 0; j < RN; j++) acc[j] = 0.0f;
        for (int k0 = 0; k0 < K; k0 += 32)
            gemm_chunk<TN>(X + (size_t)mB * ldx + k0, ldx,
                           W + (size_t)nB * ldw + k0, ldw, sX, sW, acc);
        const int row = mB + ty;
#pragma unroll
        for (int j = 0; j < RN; j++) {
            const int n = nB + tx * RN + j;
            float v = acc[j] + __ldg(bias + n);
            if (ACT) v = fmaxf(v, 0.0f);
            __stcg(Y + (size_t)row * ldy + n, v);
        }
    }
}

// Cell: Zout = tanh( YH[128,32] @ Wih^T + Zin[128,256] @ Whh^T + bih + bhh )
__device__ __forceinline__ void cell_dense(
    const float* __restrict__ YH, int ldyh,
    const float* __restrict__ Zin,
    const float* __restrict__ Wih, const float* __restrict__ Whh,
    const float* __restrict__ bih, const float* __restrict__ bhh,
    float* __restrict__ Zout, float* sX, float* sW)
{
    const int tid = threadIdx.x, ty = tid >> 4, tx = tid & 15;
    for (int tile = blockIdx.x; tile < 8 * 4; tile += gridDim.x) {
        const int mB = (tile >> 2) * 16;
        const int nB = (tile & 3) * 64;
        float acc[4] = {0.f, 0.f, 0.f, 0.f};
        // segment 1: K = 32 (one chunk)
        gemm_chunk<64>(YH + (size_t)mB * ldyh, ldyh,
                       Wih + (size_t)nB * OBS, OBS, sX, sW, acc);
        // segment 2: K = 256
        for (int k0 = 0; k0 < LAT; k0 += 32)
            gemm_chunk<64>(Zin + (size_t)mB * LAT + k0, LAT,
                           Whh + (size_t)nB * LAT + k0, LAT, sX, sW, acc);
        const int row = mB + ty;
#pragma unroll
        for (int j = 0; j < 4; j++) {
            const int n = nB + tx * 4 + j;
            float v = acc[j] + __ldg(bih + n) + __ldg(bhh + n);
            __stcg(Zout + (size_t)row * LAT + n, tanhf(v));
        }
    }
}

// ---------------------------------------------------------------------------
// Phase 2: entire AR rollout in ONE persistent kernel (6 grid barriers / step)
// ---------------------------------------------------------------------------
__global__ void __launch_bounds__(NT) phase2_kernel(
    const float* __restrict__ W1, const float* __restrict__ b1,
    const float* __restrict__ W2, const float* __restrict__ b2,
    const float* __restrict__ W3, const float* __restrict__ b3,
    const float* __restrict__ W4, const float* __restrict__ b4,
    const float* __restrict__ W5, const float* __restrict__ b5,
    const float* __restrict__ Wih, const float* __restrict__ Whh,
    const float* __restrict__ bih, const float* __restrict__ bhh,
    float* __restrict__ Z, float* __restrict__ A, float* __restrict__ B,
    float* __restrict__ out)
{
    __shared__ float sX[32 * 17];
    __shared__ float sW[32 * 68];
    unsigned epoch = 0;

    for (int t = TSTEPS; t < HORIZON; t++) {
        const float* z = Z + (size_t)t * BATCH * LAT;
        dense128<1, 64>(z, LAT, LAT, W1, LAT, b1, A, HID, HID, sX, sW);
        grid_sync(epoch);
        dense128<1, 64>(A, HID, HID, W2, HID, b2, B, HID, HID, sX, sW);
        grid_sync(epoch);
        dense128<1, 64>(B, HID, HID, W3, HID, b3, A, HID, HID, sX, sW);
        grid_sync(epoch);
        dense128<1, 64>(A, HID, HID, W4, HID, b4, B, HID, HID, sX, sW);
        grid_sync(epoch);
        dense128<0, 32>(B, HID, HID, W5, HID, b5,
                        out + (size_t)t * OBS, HORIZON * OBS, OBS, sX, sW);
        grid_sync(epoch);
        if (t < HORIZON - 1) {
            cell_dense(out + (size_t)t * OBS, HORIZON * OBS, z,
                       Wih, Whh, bih, bhh,
                       Z + (size_t)(t + 1) * BATCH * LAT, sX, sW);
            grid_sync(epoch);
        }
    }
}

// ---------------------------------------------------------------------------
// Phase 1b batched GEMM (unchanged from round 1): Y = act(X @ W^T + bias)
// ---------------------------------------------------------------------------
template<int TM, int TN, int RM, int RN, int ACT, bool SCATTER>
__global__ void gemm_k(const float* __restrict__ X, int ldx,
                       const float* __restrict__ W, int ldw,
                       const float* __restrict__ bias,
                       float* __restrict__ Y, int ldy,
                       int K, int t0)
{
    const int TK = 16;
    __shared__ float sX[TK][TM + 4];
    __shared__ float sW[TK][TN + 4];

    const int tx = threadIdx.x, ty = threadIdx.y;
    const int tid = ty * 16 + tx;
    const int mBase = blockIdx.y * TM;
    const int nBase = blockIdx.x * TN;

    float acc[RM][RN];
#pragma unroll
    for (int i = 0; i < RM; i++)
#pragma unroll
        for (int j = 0; j < RN; j++) acc[i][j] = 0.0f;

    for (int k0 = 0; k0 < K; k0 += TK) {
#pragma unroll
        for (int i = tid; i < TM * TK / 4; i += 256) {
            int row = i / (TK / 4);
            int c4  = i % (TK / 4);
            float4 v = *(const float4*)(X + (size_t)(mBase + row) * ldx + k0 + c4 * 4);
            sX[c4*4+0][row] = v.x; sX[c4*4+1][row] = v.y;
            sX[c4*4+2][row] = v.z; sX[c4*4+3][row] = v.w;
        }
#pragma unroll
        for (int i = tid; i < TN * TK / 4; i += 256) {
            int row = i / (TK / 4);
            int c4  = i % (TK / 4);
            float4 v = *(const float4*)(W + (size_t)(nBase + row) * ldw + k0 + c4 * 4);
            sW[c4*4+0][row] = v.x; sW[c4*4+1][row] = v.y;
            sW[c4*4+2][row] = v.z; sW[c4*4+3][row] = v.w;
        }
        __syncthreads();
#pragma unroll
        for (int kk = 0; kk < TK; kk++) {
            float a[RM], b[RN];
#pragma unroll
            for (int i = 0; i < RM; i++) a[i] = sX[kk][ty * RM + i];
#pragma unroll
            for (int j = 0; j < RN; j++) b[j] = sW[kk][tx * RN + j];
#pragma unroll
            for (int i = 0; i < RM; i++)
#pragma unroll
                for (int j = 0; j < RN; j++) acc[i][j] += a[i] * b[j];
        }
        __syncthreads();
    }

#pragma unroll
    for (int i = 0; i < RM; i++) {
        int r = mBase + ty * RM + i;
#pragma unroll
        for (int j = 0; j < RN; j++) {
            int n = nBase + tx * RN + j;
            float v = acc[i][j] + bias[n];
            if (ACT == 1) v = fmaxf(v, 0.0f);
            if (SCATTER) {
                int b = r & (BATCH - 1);
                int t = t0 + (r >> 7);
                Y[(size_t)b * (HORIZON * OBS) + t * OBS + n] = v;
            } else {
                Y[(size_t)r * ldy + n] = v;
            }
        }
    }
}

// ---------------------------------------------------------------------------
// Launch: ~24 graph nodes total
// ---------------------------------------------------------------------------
extern "C" void kernel_launch(void* const* d_in, const int* in_sizes, int n_in,
                              void* d_out, int out_size)
{
    const float* y   = (const float*)d_in[0];
    const float* Wih = (const float*)d_in[2];
    const float* Whh = (const float*)d_in[3];
    const float* bih = (const float*)d_in[4];
    const float* bhh = (const float*)d_in[5];
    const float* W1  = (const float*)d_in[6];
    const float* b1  = (const float*)d_in[7];
    const float* W2  = (const float*)d_in[8];
    const float* b2  = (const float*)d_in[9];
    const float* W3  = (const float*)d_in[10];
    const float* b3  = (const float*)d_in[11];
    const float* W4  = (const float*)d_in[12];
    const float* b4  = (const float*)d_in[13];
    const float* W5  = (const float*)d_in[14];
    const float* b5  = (const float*)d_in[15];
    float* out = (float*)d_out;

    float *Z, *A, *Bf;
    unsigned* bar;
    cudaGetSymbolAddress((void**)&Z,   g_Z);
    cudaGetSymbolAddress((void**)&A,   g_A);
    cudaGetSymbolAddress((void**)&Bf,  g_B);
    cudaGetSymbolAddress((void**)&bar, g_bar);

    // ---- Phase 1a: persistent recurrence over t = 0..255 ----
    cudaMemsetAsync(bar, 0, sizeof(unsigned));
    phase1a_kernel<<<NB, NT>>>(y, Wih, Whh, bih, bhh, Z);

    // ---- Phase 1b: psi over all 256 teacher-forced states (4 chunks) ----
    const dim3 blk(16, 16);
    const int CHUNK = 64;
    const int MBIG  = CHUNK * BATCH;   // 8192 rows
    const size_t ZSTATE = (size_t)BATCH * LAT;
    for (int c = 0; c < TSTEPS / CHUNK; c++) {
        const float* Xz = Z + (size_t)c * CHUNK * ZSTATE;
        gemm_k<64, 64, 4, 4, 1, false><<<dim3(HID / 64, MBIG / 64), blk>>>(
            Xz, LAT, W1, LAT, b1, A, HID, LAT, 0);
        gemm_k<64, 64, 4, 4, 1, false><<<dim3(HID / 64, MBIG / 64), blk>>>(
            A, HID, W2, HID, b2, Bf, HID, HID, 0);
        gemm_k<64, 64, 4, 4, 1, false><<<dim3(HID / 64, MBIG / 64), blk>>>(
            Bf, HID, W3, HID, b3, A, HID, HID, 0);
        gemm_k<64, 64, 4, 4, 1, false><<<dim3(HID / 64, MBIG / 64), blk>>>(
            A, HID, W4, HID, b4, Bf, HID, HID, 0);
        gemm_k<64, 32, 4, 2, 0, true><<<dim3(1, MBIG / 64), blk>>>(
            Bf, HID, W5, HID, b5, out, 0, HID, c * CHUNK);
    }

    // ---- Phase 2: persistent AR rollout t = 256..511 ----
    cudaMemsetAsync(bar, 0, sizeof(unsigned));
    phase2_kernel<<<NB, NT>>>(W1, b1, W2, b2, W3, b3, W4, b4, W5, b5,
                              Wih, Whh, bih, bhh, Z, A, Bf, out);
}

// round 3
// speedup vs baseline: 1.9029x; 1.9029x over previous
#include <cuda_runtime.h>
#include <math.h>

#define BATCH   128
#define TSTEPS  256
#define HORIZON 512
#define OBS     32
#define LAT     256
#define HID     1024
#define NB2     148     // phase-2 persistent grid
#define ZSTRIDE (BATCH * LAT)   // 32768 floats per timestep state

// ---------------------------------------------------------------------------
// Scratch
// ---------------------------------------------------------------------------
__device__ float g_Z[(size_t)(HORIZON + 1) * ZSTRIDE];        // 67 MB
__device__ float g_A[(size_t)128 * BATCH * HID];              // 64 MB
__device__ float g_B[(size_t)128 * BATCH * HID];              // 64 MB
__device__ float g_C[BATCH * LAT];                            // cell Whh partial
__device__ unsigned g_bar;

// ---------------------------------------------------------------------------
// Grid barrier (hot spin, release/acquire via threadfence)
// ---------------------------------------------------------------------------
__device__ __forceinline__ void gsync(unsigned& target) {
    target += gridDim.x;
    __syncthreads();
    if (threadIdx.x == 0) {
        __threadfence();
        atomicAdd(&g_bar, 1u);
        while (*((volatile unsigned*)&g_bar) < target) {}
        __threadfence();
    }
    __syncthreads();
}

// ---------------------------------------------------------------------------
// Phase 1a: barrier-free. CTA b owns batch row b for all 256 steps.
// ---------------------------------------------------------------------------
__global__ void __launch_bounds__(256) phase1a_kernel(
    const float* __restrict__ y,
    const float* __restrict__ Wih, const float* __restrict__ Whh,
    const float* __restrict__ bih, const float* __restrict__ bhh,
    float* __restrict__ Z)
{
    const int b = blockIdx.x, tid = threadIdx.x;
    __shared__ float sz[LAT];
    __shared__ float sy[OBS];

    sz[tid] = 0.0f;
    __stcg(Z + (size_t)b * LAT + tid, 0.0f);
    float bsum = __ldg(bih + tid) + __ldg(bhh + tid);

    float4 wi[8];
    const float4* wip = (const float4*)(Wih + (size_t)tid * OBS);
#pragma unroll
    for (int k = 0; k < 8; k++) wi[k] = __ldg(wip + k);
    const float4* wh = (const float4*)(Whh + (size_t)tid * LAT);
    __syncthreads();

    for (int t = 0; t < TSTEPS; t++) {
        if (tid < OBS) sy[tid] = __ldg(y + ((size_t)b * TSTEPS + t) * OBS + tid);
        __syncthreads();
        float acc = bsum;
#pragma unroll
        for (int k = 0; k < 8; k++) {
            float4 w = wi[k];
            acc += sy[k*4+0]*w.x + sy[k*4+1]*w.y + sy[k*4+2]*w.z + sy[k*4+3]*w.w;
        }
#pragma unroll 8
        for (int k = 0; k < 64; k++) {
            float4 w = __ldg(wh + k);
            acc += sz[k*4+0]*w.x + sz[k*4+1]*w.y + sz[k*4+2]*w.z + sz[k*4+3]*w.w;
        }
        float zn = tanhf(acc);
        __syncthreads();
        sz[tid] = zn;
        __stcg(Z + ((size_t)t + 1) * ZSTRIDE + (size_t)b * LAT + tid, zn);
    }
}

// ---------------------------------------------------------------------------
// Phase 1b GEMM: Y = act(X[M,K] @ W[N,K]^T + bias). 256 thr, 128x64 tile,
// RM=8 x RN=4 microtile, TK=16, register-double-buffered global prefetch.
// ---------------------------------------------------------------------------
template<int ACT>
__global__ void __launch_bounds__(256) gemm_big(
    const float* __restrict__ X, int ldx,
    const float* __restrict__ W, int ldw,
    const float* __restrict__ bias,
    float* __restrict__ Y, int ldy, int K)
{
    __shared__ float sX[16 * 132];
    __shared__ float sW[16 * 68];
    const int tid = threadIdx.x;
    const int ty = tid >> 4, tx = tid & 15;
    const int mB = blockIdx.y * 128, nB = blockIdx.x * 64;
    const int xr = tid >> 2, xc = tid & 3;

    const float* Xp0 = X + (size_t)(mB + xr) * ldx + xc * 4;
    const float* Xp1 = Xp0 + (size_t)64 * ldx;
    const float* Wp  = W + (size_t)(nB + xr) * ldw + xc * 4;

    float4 xv0 = __ldg((const float4*)Xp0);
    float4 xv1 = __ldg((const float4*)Xp1);
    float4 wv  = __ldg((const float4*)Wp);

    float acc[8][4];
#pragma unroll
    for (int i = 0; i < 8; i++)
#pragma unroll
        for (int j = 0; j < 4; j++) acc[i][j] = 0.0f;

    for (int k0 = 0;;) {
        sX[(xc*4+0)*132 + xr] = xv0.x; sX[(xc*4+1)*132 + xr] = xv0.y;
        sX[(xc*4+2)*132 + xr] = xv0.z; sX[(xc*4+3)*132 + xr] = xv0.w;
        sX[(xc*4+0)*132 + xr+64] = xv1.x; sX[(xc*4+1)*132 + xr+64] = xv1.y;
        sX[(xc*4+2)*132 + xr+64] = xv1.z; sX[(xc*4+3)*132 + xr+64] = xv1.w;
        sW[(xc*4+0)*68 + xr] = wv.x; sW[(xc*4+1)*68 + xr] = wv.y;
        sW[(xc*4+2)*68 + xr] = wv.z; sW[(xc*4+3)*68 + xr] = wv.w;
        __syncthreads();

        const int k1 = k0 + 16;
        if (k1 < K) {
            xv0 = __ldg((const float4*)(Xp0 + k1));
            xv1 = __ldg((const float4*)(Xp1 + k1));
            wv  = __ldg((const float4*)(Wp  + k1));
        }
#pragma unroll
        for (int kk = 0; kk < 16; kk++) {
            float4 a0 = *(const float4*)&sX[kk*132 + ty*8];
            float4 a1 = *(const float4*)&sX[kk*132 + ty*8 + 4];
            float4 b  = *(const float4*)&sW[kk*68 + tx*4];
            acc[0][0]+=a0.x*b.x; acc[0][1]+=a0.x*b.y; acc[0][2]+=a0.x*b.z; acc[0][3]+=a0.x*b.w;
            acc[1][0]+=a0.y*b.x; acc[1][1]+=a0.y*b.y; acc[1][2]+=a0.y*b.z; acc[1][3]+=a0.y*b.w;
            acc[2][0]+=a0.z*b.x; acc[2][1]+=a0.z*b.y; acc[2][2]+=a0.z*b.z; acc[2][3]+=a0.z*b.w;
            acc[3][0]+=a0.w*b.x; acc[3][1]+=a0.w*b.y; acc[3][2]+=a0.w*b.z; acc[3][3]+=a0.w*b.w;
            acc[4][0]+=a1.x*b.x; acc[4][1]+=a1.x*b.y; acc[4][2]+=a1.x*b.z; acc[4][3]+=a1.x*b.w;
            acc[5][0]+=a1.y*b.x; acc[5][1]+=a1.y*b.y; acc[5][2]+=a1.y*b.z; acc[5][3]+=a1.y*b.w;
            acc[6][0]+=a1.z*b.x; acc[6][1]+=a1.z*b.y; acc[6][2]+=a1.z*b.z; acc[6][3]+=a1.z*b.w;
            acc[7][0]+=a1.w*b.x; acc[7][1]+=a1.w*b.y; acc[7][2]+=a1.w*b.z; acc[7][3]+=a1.w*b.w;
        }
        __syncthreads();
        if (k1 >= K) break;
        k0 = k1;
    }

    float4 bb = __ldg((const float4*)(bias + nB + tx * 4));
#pragma unroll
    for (int i = 0; i < 8; i++) {
        float4 v = make_float4(acc[i][0]+bb.x, acc[i][1]+bb.y, acc[i][2]+bb.z, acc[i][3]+bb.w);
        if (ACT) { v.x=fmaxf(v.x,0.f); v.y=fmaxf(v.y,0.f); v.z=fmaxf(v.z,0.f); v.w=fmaxf(v.w,0.f); }
        *(float4*)(Y + (size_t)(mB + ty*8 + i) * ldy + nB + tx * 4) = v;
    }
}

// Phase 1b output layer: N=32, scatter into out[b,t,s]. 128x32 tile, RM=8 x RN=2.
__global__ void __launch_bounds__(256) gemm_out(
    const float* __restrict__ X, int ldx,
    const float* __restrict__ W, int ldw,
    const float* __restrict__ bias,
    float* __restrict__ out, int K, int t0)
{
    __shared__ float sX[16 * 132];
    __shared__ float sW[16 * 36];
    const int tid = threadIdx.x;
    const int ty = tid >> 4, tx = tid & 15;
    const int mB = blockIdx.y * 128;
    const int xr = tid >> 2, xc = tid & 3;

    const float* Xp0 = X + (size_t)(mB + xr) * ldx + xc * 4;
    const float* Xp1 = Xp0 + (size_t)64 * ldx;
    const bool wp = tid < 128;
    const float* Wp = W + (size_t)xr * ldw + xc * 4;   // xr in 0..31 when wp

    float4 xv0 = __ldg((const float4*)Xp0);
    float4 xv1 = __ldg((const float4*)Xp1);
    float4 wv = make_float4(0,0,0,0);
    if (wp) wv = __ldg((const float4*)Wp);

    float acc[8][2];
#pragma unroll
    for (int i = 0; i < 8; i++) { acc[i][0] = 0.f; acc[i][1] = 0.f; }

    for (int k0 = 0;;) {
        sX[(xc*4+0)*132 + xr] = xv0.x; sX[(xc*4+1)*132 + xr] = xv0.y;
        sX[(xc*4+2)*132 + xr] = xv0.z; sX[(xc*4+3)*132 + xr] = xv0.w;
        sX[(xc*4+0)*132 + xr+64] = xv1.x; sX[(xc*4+1)*132 + xr+64] = xv1.y;
        sX[(xc*4+2)*132 + xr+64] = xv1.z; sX[(xc*4+3)*132 + xr+64] = xv1.w;
        if (wp) {
            sW[(xc*4+0)*36 + xr] = wv.x; sW[(xc*4+1)*36 + xr] = wv.y;
            sW[(xc*4+2)*36 + xr] = wv.z; sW[(xc*4+3)*36 + xr] = wv.w;
        }
        __syncthreads();
        const int k1 = k0 + 16;
        if (k1 < K) {
            xv0 = __ldg((const float4*)(Xp0 + k1));
            xv1 = __ldg((const float4*)(Xp1 + k1));
            if (wp) wv = __ldg((const float4*)(Wp + k1));
        }
#pragma unroll
        for (int kk = 0; kk < 16; kk++) {
            float4 a0 = *(const float4*)&sX[kk*132 + ty*8];
            float4 a1 = *(const float4*)&sX[kk*132 + ty*8 + 4];
            float2 b  = *(const float2*)&sW[kk*36 + tx*2];
            acc[0][0]+=a0.x*b.x; acc[0][1]+=a0.x*b.y;
            acc[1][0]+=a0.y*b.x; acc[1][1]+=a0.y*b.y;
            acc[2][0]+=a0.z*b.x; acc[2][1]+=a0.z*b.y;
            acc[3][0]+=a0.w*b.x; acc[3][1]+=a0.w*b.y;
            acc[4][0]+=a1.x*b.x; acc[4][1]+=a1.x*b.y;
            acc[5][0]+=a1.y*b.x; acc[5][1]+=a1.y*b.y;
            acc[6][0]+=a1.z*b.x; acc[6][1]+=a1.z*b.y;
            acc[7][0]+=a1.w*b.x; acc[7][1]+=a1.w*b.y;
        }
        __syncthreads();
        if (k1 >= K) break;
        k0 = k1;
    }

    float2 bb = *(const float2*)(bias + tx * 2);
#pragma unroll
    for (int i = 0; i < 8; i++) {
        int r = mB + ty * 8 + i;
        int b = r & (BATCH - 1);
        int t = t0 + (r >> 7);
        float2 v = make_float2(acc[i][0] + bb.x, acc[i][1] + bb.y);
        *(float2*)(out + ((size_t)b * HORIZON + t) * OBS + tx * 2) = v;
    }
}

// ---------------------------------------------------------------------------
// Phase 2 tile primitives (128-thread CTAs). 16x64 tile, RM=2 x RN=4, TK=32.
// X via __ldcg (cross-CTA in-kernel), W via __ldg, Y via __stcg.
// ---------------------------------------------------------------------------
__device__ __forceinline__ void mlp_tile(
    int mB, int nB,
    const float* __restrict__ X, int ldx, int K,
    const float* __restrict__ W, int ldw,
    const float* __restrict__ bias, bool relu,
    float* __restrict__ Y, int ldy,
    float* sX, float* sW)
{
    const int tid = threadIdx.x;
    const int ty = tid >> 4, tx = tid & 15;
    const int xr = tid >> 3, xc = tid & 7;

    const float* Xp = X + (size_t)(mB + xr) * ldx + xc * 4;
    const float* Wp = W + (size_t)(nB + xr) * ldw + xc * 4;

    float4 xv = __ldcg((const float4*)Xp);
    float4 wv[4];
#pragma unroll
    for (int j = 0; j < 4; j++)
        wv[j] = __ldg((const float4*)(Wp + (size_t)(j * 16) * ldw));

    float acc[2][4];
#pragma unroll
    for (int i = 0; i < 2; i++)
#pragma unroll
        for (int j = 0; j < 4; j++) acc[i][j] = 0.0f;

    for (int k0 = 0;;) {
        sX[(xc*4+0)*17 + xr] = xv.x; sX[(xc*4+1)*17 + xr] = xv.y;
        sX[(xc*4+2)*17 + xr] = xv.z; sX[(xc*4+3)*17 + xr] = xv.w;
#pragma unroll
        for (int j = 0; j < 4; j++) {
            int wr = xr + j * 16;
            sW[(xc*4+0)*68 + wr] = wv[j].x; sW[(xc*4+1)*68 + wr] = wv[j].y;
            sW[(xc*4+2)*68 + wr] = wv[j].z; sW[(xc*4+3)*68 + wr] = wv[j].w;
        }
        __syncthreads();
        const int k1 = k0 + 32;
        if (k1 < K) {
            xv = __ldcg((const float4*)(Xp + k1));
#pragma unroll
            for (int j = 0; j < 4; j++)
                wv[j] = __ldg((const float4*)(Wp + (size_t)(j * 16) * ldw + k1));
        }
#pragma unroll
        for (int kk = 0; kk < 32; kk++) {
            float a0 = sX[kk*17 + ty];
            float a1 = sX[kk*17 + ty + 8];
            float4 b = *(const float4*)&sW[kk*68 + tx*4];
            acc[0][0]+=a0*b.x; acc[0][1]+=a0*b.y; acc[0][2]+=a0*b.z; acc[0][3]+=a0*b.w;
            acc[1][0]+=a1*b.x; acc[1][1]+=a1*b.y; acc[1][2]+=a1*b.z; acc[1][3]+=a1*b.w;
        }
        __syncthreads();
        if (k1 >= K) break;
        k0 = k1;
    }

    float4 bb = make_float4(0, 0, 0, 0);
    if (bias) bb = __ldg((const float4*)(bias + nB + tx * 4));
#pragma unroll
    for (int i = 0; i < 2; i++) {
        int row = mB + ty + i * 8;
        float4 v = make_float4(acc[i][0]+bb.x, acc[i][1]+bb.y, acc[i][2]+bb.z, acc[i][3]+bb.w);
        if (relu) { v.x=fmaxf(v.x,0.f); v.y=fmaxf(v.y,0.f); v.z=fmaxf(v.z,0.f); v.w=fmaxf(v.w,0.f); }
        __stcg((float4*)(Y + (size_t)row * ldy + nB + tx * 4), v);
    }
}

// L5 tile: 16x32, output -> out[b, t, :]
__device__ __forceinline__ void l5_tile(
    int mB, const float* __restrict__ X, int ldx,
    const float* __restrict__ W5, const float* __restrict__ b5,
    float* __restrict__ out, int t,
    float* sX, float* sW)
{
    const int tid = threadIdx.x;
    const int ty = tid >> 4, tx = tid & 15;
    const int xr = tid >> 3, xc = tid & 7;
    const int K = HID;

    const float* Xp = X + (size_t)(mB + xr) * ldx + xc * 4;
    const float* Wp = W5 + (size_t)xr * HID + xc * 4;   // rows xr, xr+16

    float4 xv = __ldcg((const float4*)Xp);
    float4 wv[2];
    wv[0] = __ldg((const float4*)Wp);
    wv[1] = __ldg((const float4*)(Wp + (size_t)16 * HID));

    float acc[2][2] = {{0.f,0.f},{0.f,0.f}};

    for (int k0 = 0;;) {
        sX[(xc*4+0)*17 + xr] = xv.x; sX[(xc*4+1)*17 + xr] = xv.y;
        sX[(xc*4+2)*17 + xr] = xv.z; sX[(xc*4+3)*17 + xr] = xv.w;
#pragma unroll
        for (int j = 0; j < 2; j++) {
            int wr = xr + j * 16;
            sW[(xc*4+0)*36 + wr] = wv[j].x; sW[(xc*4+1)*36 + wr] = wv[j].y;
            sW[(xc*4+2)*36 + wr] = wv[j].z; sW[(xc*4+3)*36 + wr] = wv[j].w;
        }
        __syncthreads();
        const int k1 = k0 + 32;
        if (k1 < K) {
            xv = __ldcg((const float4*)(Xp + k1));
            wv[0] = __ldg((const float4*)(Wp + k1));
            wv[1] = __ldg((const float4*)(Wp + (size_t)16 * HID + k1));
        }
#pragma unroll
        for (int kk = 0; kk < 32; kk++) {
            float a0 = sX[kk*17 + ty];
            float a1 = sX[kk*17 + ty + 8];
            float2 b = *(const float2*)&sW[kk*36 + tx*2];
            acc[0][0]+=a0*b.x; acc[0][1]+=a0*b.y;
            acc[1][0]+=a1*b.x; acc[1][1]+=a1*b.y;
        }
        __syncthreads();
        if (k1 >= K) break;
        k0 = k1;
    }

    float2 bb = *(const float2*)(b5 + tx * 2);
#pragma unroll
    for (int i = 0; i < 2; i++) {
        int row = mB + ty + i * 8;   // batch index
        float2 v = make_float2(acc[i][0] + bb.x, acc[i][1] + bb.y);
        __stcg((float2*)(out + ((size_t)row * HORIZON + t) * OBS + tx * 2), v);
    }
}

// ---------------------------------------------------------------------------
// Phase 2: persistent AR rollout. grid = 148 x 128 threads. 6 barriers/step.
// ---------------------------------------------------------------------------
__global__ void __launch_bounds__(128) phase2_kernel(
    const float* __restrict__ W1, const float* __restrict__ b1,
    const float* __restrict__ W2, const float* __restrict__ b2,
    const float* __restrict__ W3, const float* __restrict__ b3,
    const float* __restrict__ W4, const float* __restrict__ b4,
    const float* __restrict__ W5, const float* __restrict__ b5,
    const float* __restrict__ Wih, const float* __restrict__ Whh,
    const float* __restrict__ bih, const float* __restrict__ bhh,
    float* __restrict__ Z, float* __restrict__ A, float* __restrict__ B,
    float* __restrict__ C, float* __restrict__ out)
{
    __shared__ float sX[32 * 17];
    __shared__ float sW[32 * 68];
    unsigned target = 0;
    const int bid = blockIdx.x;
    const int tid = threadIdx.x;

    for (int t = TSTEPS; t < HORIZON; t++) {
        const float* z = Z + (size_t)t * ZSTRIDE;
        if (bid < 128)
            mlp_tile((bid >> 4) * 16, (bid & 15) * 64, z, LAT, LAT,
                     W1, LAT, b1, true, A, HID, sX, sW);
        gsync(target);
        if (bid < 128)
            mlp_tile((bid >> 4) * 16, (bid & 15) * 64, A, HID, HID,
                     W2, HID, b2, true, B, HID, sX, sW);
        gsync(target);
        if (bid < 128)
            mlp_tile((bid >> 4) * 16, (bid & 15) * 64, B, HID, HID,
                     W3, HID, b3, true, A, HID, sX, sW);
        gsync(target);
        if (bid < 128)
            mlp_tile((bid >> 4) * 16, (bid & 15) * 64, A, HID, HID,
                     W4, HID, b4, true, B, HID, sX, sW);
        gsync(target);
        // R5: L5 (8 tiles) in parallel with z @ Whh^T (32 tiles)
        if (bid < 8) {
            l5_tile(bid * 16, B, HID, W5, b5, out, t, sX, sW);
        } else if (bid < 40) {
            int tl = bid - 8;
            mlp_tile((tl >> 2) * 16, (tl & 3) * 64, z, LAT, LAT,
                     Whh, LAT, (const float*)0, false, C, LAT, sX, sW);
        }
        gsync(target);
        // R6: z_{t+1} = tanh(C + yh @ Wih^T + bih + bhh)
        if (t < HORIZON - 1 && bid < 128) {
            const int row = bid;
            if (tid < OBS)
                sX[tid] = __ldcg(out + ((size_t)row * HORIZON + t) * OBS + tid);
            __syncthreads();
#pragma unroll
            for (int p = 0; p < 2; p++) {
                int n = tid + p * 128;
                float acc = __ldcg(C + (size_t)row * LAT + n)
                          + __ldg(bih + n) + __ldg(bhh + n);
                const float4* wr = (const float4*)(Wih + (size_t)n * OBS);
#pragma unroll
                for (int k = 0; k < 8; k++) {
                    float4 w = __ldg(wr + k);
                    acc += sX[k*4+0]*w.x + sX[k*4+1]*w.y + sX[k*4+2]*w.z + sX[k*4+3]*w.w;
                }
                __stcg(Z + ((size_t)t + 1) * ZSTRIDE + (size_t)row * LAT + n, tanhf(acc));
            }
        }
        gsync(target);
    }
}

// ---------------------------------------------------------------------------
// Launch: 13 graph nodes
// ---------------------------------------------------------------------------
extern "C" void kernel_launch(void* const* d_in, const int* in_sizes, int n_in,
                              void* d_out, int out_size)
{
    const float* y   = (const float*)d_in[0];
    const float* Wih = (const float*)d_in[2];
    const float* Whh = (const float*)d_in[3];
    const float* bih = (const float*)d_in[4];
    const float* bhh = (const float*)d_in[5];
    const float* W1  = (const float*)d_in[6];
    const float* b1  = (const float*)d_in[7];
    const float* W2  = (const float*)d_in[8];
    const float* b2  = (const float*)d_in[9];
    const float* W3  = (const float*)d_in[10];
    const float* b3  = (const float*)d_in[11];
    const float* W4  = (const float*)d_in[12];
    const float* b4  = (const float*)d_in[13];
    const float* W5  = (const float*)d_in[14];
    const float* b5  = (const float*)d_in[15];
    float* out = (float*)d_out;

    float *Z, *A, *Bf, *C;
    unsigned* bar;
    cudaGetSymbolAddress((void**)&Z,   g_Z);
    cudaGetSymbolAddress((void**)&A,   g_A);
    cudaGetSymbolAddress((void**)&Bf,  g_B);
    cudaGetSymbolAddress((void**)&C,   g_C);
    cudaGetSymbolAddress((void**)&bar, g_bar);

    // Phase 1a: barrier-free recurrence
    phase1a_kernel<<<BATCH, 256>>>(y, Wih, Whh, bih, bhh, Z);

    // Phase 1b: psi over 256 teacher-forced states, 2 chunks of 128 steps
    const int CHUNK = 128;
    const int MBIG  = CHUNK * BATCH;   // 16384
    for (int c = 0; c < TSTEPS / CHUNK; c++) {
        const float* Xz = Z + (size_t)c * CHUNK * ZSTRIDE;
        gemm_big<1><<<dim3(HID/64, MBIG/128), 256>>>(Xz, LAT, W1, LAT, b1, A, HID, LAT);
        gemm_big<1><<<dim3(HID/64, MBIG/128), 256>>>(A, HID, W2, HID, b2, Bf, HID, HID);
        gemm_big<1><<<dim3(HID/64, MBIG/128), 256>>>(Bf, HID, W3, HID, b3, A, HID, HID);
        gemm_big<1><<<dim3(HID/64, MBIG/128), 256>>>(A, HID, W4, HID, b4, Bf, HID, HID);
        gemm_out<<<dim3(1, MBIG/128), 256>>>(Bf, HID, W5, HID, b5, out, HID, c * CHUNK);
    }

    // Phase 2: persistent AR rollout
    cudaMemsetAsync(bar, 0, sizeof(unsigned));
    phase2_kernel<<<NB2, 128>>>(W1, b1, W2, b2, W3, b3, W4, b4, W5, b5,
                                Wih, Whh, bih, bhh, Z, A, Bf, C, out);
}

// round 4
// speedup vs baseline: 2.0808x; 1.0935x over previous
#include <cuda_runtime.h>
#include <math.h>

#define BATCH   128
#define TSTEPS  256
#define HORIZON 512
#define OBS     32
#define LAT     256
#define HID     1024
#define NB2     148
#define ZSTRIDE (BATCH * LAT)

// ---------------------------------------------------------------------------
// Scratch
// ---------------------------------------------------------------------------
__device__ float g_Z[(size_t)(HORIZON + 1) * ZSTRIDE];
__device__ float g_A[(size_t)128 * BATCH * HID];
__device__ float g_B[(size_t)128 * BATCH * HID];
__device__ float g_C[BATCH * LAT];
__device__ unsigned g_bar;

// ---------------------------------------------------------------------------
// f32x2 packed-FMA helpers (sm_100+; ptxas never emits FFMA2 from C++)
// ---------------------------------------------------------------------------
typedef unsigned long long u64;
__device__ __forceinline__ u64 f2dup(float s) {
    u64 r; asm("mov.b64 %0, {%1, %1};" : "=l"(r) : "f"(s)); return r;
}
__device__ __forceinline__ void f2fma(u64& d, u64 a, u64 b) {
    asm("fma.rn.f32x2 %0, %1, %2, %0;" : "+l"(d) : "l"(a), "l"(b));
}
__device__ __forceinline__ float2 f2unpack(u64 v) {
    float2 r; asm("mov.b64 {%0, %1}, %2;" : "=f"(r.x), "=f"(r.y) : "l"(v)); return r;
}

// ---------------------------------------------------------------------------
// Grid barrier
// ---------------------------------------------------------------------------
__device__ __forceinline__ void gsync(unsigned& target) {
    target += gridDim.x;
    __syncthreads();
    if (threadIdx.x == 0) {
        __threadfence();
        atomicAdd(&g_bar, 1u);
        while (*((volatile unsigned*)&g_bar) < target) {}
        __threadfence();
    }
    __syncthreads();
}

// ---------------------------------------------------------------------------
// Phase 1a: barrier-free recurrence. CTA b owns batch row b.
// ---------------------------------------------------------------------------
__global__ void __launch_bounds__(256) phase1a_kernel(
    const float* __restrict__ y,
    const float* __restrict__ Wih, const float* __restrict__ Whh,
    const float* __restrict__ bih, const float* __restrict__ bhh,
    float* __restrict__ Z)
{
    const int b = blockIdx.x, tid = threadIdx.x;
    __shared__ float sz[LAT];
    __shared__ float sy[OBS];

    sz[tid] = 0.0f;
    __stcg(Z + (size_t)b * LAT + tid, 0.0f);
    float bsum = __ldg(bih + tid) + __ldg(bhh + tid);

    float4 wi[8];
    const float4* wip = (const float4*)(Wih + (size_t)tid * OBS);
#pragma unroll
    for (int k = 0; k < 8; k++) wi[k] = __ldg(wip + k);
    const float4* wh = (const float4*)(Whh + (size_t)tid * LAT);
    __syncthreads();

    for (int t = 0; t < TSTEPS; t++) {
        if (tid < OBS) sy[tid] = __ldg(y + ((size_t)b * TSTEPS + t) * OBS + tid);
        __syncthreads();
        float acc = bsum;
#pragma unroll
        for (int k = 0; k < 8; k++) {
            float4 w = wi[k];
            acc += sy[k*4+0]*w.x + sy[k*4+1]*w.y + sy[k*4+2]*w.z + sy[k*4+3]*w.w;
        }
#pragma unroll 8
        for (int k = 0; k < 64; k++) {
            float4 w = __ldg(wh + k);
            acc += sz[k*4+0]*w.x + sz[k*4+1]*w.y + sz[k*4+2]*w.z + sz[k*4+3]*w.w;
        }
        float zn = tanhf(acc);
        __syncthreads();
        sz[tid] = zn;
        __stcg(Z + ((size_t)t + 1) * ZSTRIDE + (size_t)b * LAT + tid, zn);
    }
}

// ---------------------------------------------------------------------------
// Phase 1b GEMM (f32x2): Y = act(X[M,K] @ W[N,K]^T + bias).
// 256 thr, 128x128 tile, 8m x 8n per thread, m-paired FFMA2, TK=16.
// ---------------------------------------------------------------------------
template<int ACT>
__global__ void __launch_bounds__(256, 2) gemm_big(
    const float* __restrict__ X, int ldx,
    const float* __restrict__ W, int ldw,
    const float* __restrict__ bias,
    float* __restrict__ Y, int ldy, int K)
{
    __shared__ __align__(16) float sX[16 * 132];
    __shared__ __align__(16) float sW[16 * 132];
    const int tid = threadIdx.x;
    const int ty = tid >> 4, tx = tid & 15;
    const int mB = blockIdx.y * 128, nB = blockIdx.x * 128;
    const int xr = tid >> 2, xc = tid & 3;

    const float* Xp0 = X + (size_t)(mB + xr) * ldx + xc * 4;
    const float* Xp1 = Xp0 + (size_t)64 * ldx;
    const float* Wp0 = W + (size_t)(nB + xr) * ldw + xc * 4;
    const float* Wp1 = Wp0 + (size_t)64 * ldw;

    float4 xv0 = __ldg((const float4*)Xp0);
    float4 xv1 = __ldg((const float4*)Xp1);
    float4 wv0 = __ldg((const float4*)Wp0);
    float4 wv1 = __ldg((const float4*)Wp1);

    u64 acc[4][8];
#pragma unroll
    for (int i = 0; i < 4; i++)
#pragma unroll
        for (int j = 0; j < 8; j++) acc[i][j] = 0ull;

    for (int k0 = 0;;) {
        sX[(xc*4+0)*132 + xr] = xv0.x; sX[(xc*4+1)*132 + xr] = xv0.y;
        sX[(xc*4+2)*132 + xr] = xv0.z; sX[(xc*4+3)*132 + xr] = xv0.w;
        sX[(xc*4+0)*132 + xr+64] = xv1.x; sX[(xc*4+1)*132 + xr+64] = xv1.y;
        sX[(xc*4+2)*132 + xr+64] = xv1.z; sX[(xc*4+3)*132 + xr+64] = xv1.w;
        sW[(xc*4+0)*132 + xr] = wv0.x; sW[(xc*4+1)*132 + xr] = wv0.y;
        sW[(xc*4+2)*132 + xr] = wv0.z; sW[(xc*4+3)*132 + xr] = wv0.w;
        sW[(xc*4+0)*132 + xr+64] = wv1.x; sW[(xc*4+1)*132 + xr+64] = wv1.y;
        sW[(xc*4+2)*132 + xr+64] = wv1.z; sW[(xc*4+3)*132 + xr+64] = wv1.w;
        __syncthreads();

        const int k1 = k0 + 16;
        if (k1 < K) {
            xv0 = __ldg((const float4*)(Xp0 + k1));
            xv1 = __ldg((const float4*)(Xp1 + k1));
            wv0 = __ldg((const float4*)(Wp0 + k1));
            wv1 = __ldg((const float4*)(Wp1 + k1));
        }
#pragma unroll
        for (int kk = 0; kk < 16; kk++) {
            ulonglong2 aA = *(const ulonglong2*)&sX[kk*132 + ty*8];
            ulonglong2 aB = *(const ulonglong2*)&sX[kk*132 + ty*8 + 4];
            float4 b0 = *(const float4*)&sW[kk*132 + tx*8];
            float4 b1 = *(const float4*)&sW[kk*132 + tx*8 + 4];
            u64 bd[8];
            bd[0]=f2dup(b0.x); bd[1]=f2dup(b0.y); bd[2]=f2dup(b0.z); bd[3]=f2dup(b0.w);
            bd[4]=f2dup(b1.x); bd[5]=f2dup(b1.y); bd[6]=f2dup(b1.z); bd[7]=f2dup(b1.w);
#pragma unroll
            for (int j = 0; j < 8; j++) {
                f2fma(acc[0][j], aA.x, bd[j]);
                f2fma(acc[1][j], aA.y, bd[j]);
                f2fma(acc[2][j], aB.x, bd[j]);
                f2fma(acc[3][j], aB.y, bd[j]);
            }
        }
        __syncthreads();
        if (k1 >= K) break;
        k0 = k1;
    }

    float4 bb0 = __ldg((const float4*)(bias + nB + tx * 8));
    float4 bb1 = __ldg((const float4*)(bias + nB + tx * 8 + 4));
#pragma unroll
    for (int mp = 0; mp < 4; mp++) {
        float2 u[8];
#pragma unroll
        for (int j = 0; j < 8; j++) u[j] = f2unpack(acc[mp][j]);
        float4 r0a = make_float4(u[0].x+bb0.x, u[1].x+bb0.y, u[2].x+bb0.z, u[3].x+bb0.w);
        float4 r0b = make_float4(u[4].x+bb1.x, u[5].x+bb1.y, u[6].x+bb1.z, u[7].x+bb1.w);
        float4 r1a = make_float4(u[0].y+bb0.x, u[1].y+bb0.y, u[2].y+bb0.z, u[3].y+bb0.w);
        float4 r1b = make_float4(u[4].y+bb1.x, u[5].y+bb1.y, u[6].y+bb1.z, u[7].y+bb1.w);
        if (ACT) {
            r0a.x=fmaxf(r0a.x,0.f); r0a.y=fmaxf(r0a.y,0.f); r0a.z=fmaxf(r0a.z,0.f); r0a.w=fmaxf(r0a.w,0.f);
            r0b.x=fmaxf(r0b.x,0.f); r0b.y=fmaxf(r0b.y,0.f); r0b.z=fmaxf(r0b.z,0.f); r0b.w=fmaxf(r0b.w,0.f);
            r1a.x=fmaxf(r1a.x,0.f); r1a.y=fmaxf(r1a.y,0.f); r1a.z=fmaxf(r1a.z,0.f); r1a.w=fmaxf(r1a.w,0.f);
            r1b.x=fmaxf(r1b.x,0.f); r1b.y=fmaxf(r1b.y,0.f); r1b.z=fmaxf(r1b.z,0.f); r1b.w=fmaxf(r1b.w,0.f);
        }
        const int row0 = mB + ty * 8 + mp * 2;
        float* y0 = Y + (size_t)row0 * ldy + nB + tx * 8;
        float* y1 = y0 + ldy;
        *(float4*)y0 = r0a; *(float4*)(y0 + 4) = r0b;
        *(float4*)y1 = r1a; *(float4*)(y1 + 4) = r1b;
    }
}

// ---------------------------------------------------------------------------
// Phase 1b output layer: N=32, scatter into out[b,t,s]. 128x32 tile.
// ---------------------------------------------------------------------------
__global__ void __launch_bounds__(256) gemm_out(
    const float* __restrict__ X, int ldx,
    const float* __restrict__ W, int ldw,
    const float* __restrict__ bias,
    float* __restrict__ out, int K, int t0)
{
    __shared__ __align__(16) float sX[16 * 132];
    __shared__ __align__(16) float sW[16 * 36];
    const int tid = threadIdx.x;
    const int ty = tid >> 4, tx = tid & 15;
    const int mB = blockIdx.y * 128;
    const int xr = tid >> 2, xc = tid & 3;

    const float* Xp0 = X + (size_t)(mB + xr) * ldx + xc * 4;
    const float* Xp1 = Xp0 + (size_t)64 * ldx;
    const bool wp = tid < 128;
    const float* Wp = W + (size_t)xr * ldw + xc * 4;

    float4 xv0 = __ldg((const float4*)Xp0);
    float4 xv1 = __ldg((const float4*)Xp1);
    float4 wv = make_float4(0,0,0,0);
    if (wp) wv = __ldg((const float4*)Wp);

    float acc[8][2];
#pragma unroll
    for (int i = 0; i < 8; i++) { acc[i][0] = 0.f; acc[i][1] = 0.f; }

    for (int k0 = 0;;) {
        sX[(xc*4+0)*132 + xr] = xv0.x; sX[(xc*4+1)*132 + xr] = xv0.y;
        sX[(xc*4+2)*132 + xr] = xv0.z; sX[(xc*4+3)*132 + xr] = xv0.w;
        sX[(xc*4+0)*132 + xr+64] = xv1.x; sX[(xc*4+1)*132 + xr+64] = xv1.y;
        sX[(xc*4+2)*132 + xr+64] = xv1.z; sX[(xc*4+3)*132 + xr+64] = xv1.w;
        if (wp) {
            sW[(xc*4+0)*36 + xr] = wv.x; sW[(xc*4+1)*36 + xr] = wv.y;
            sW[(xc*4+2)*36 + xr] = wv.z; sW[(xc*4+3)*36 + xr] = wv.w;
        }
        __syncthreads();
        const int k1 = k0 + 16;
        if (k1 < K) {
            xv0 = __ldg((const float4*)(Xp0 + k1));
            xv1 = __ldg((const float4*)(Xp1 + k1));
            if (wp) wv = __ldg((const float4*)(Wp + k1));
        }
#pragma unroll
        for (int kk = 0; kk < 16; kk++) {
            float4 a0 = *(const float4*)&sX[kk*132 + ty*8];
            float4 a1 = *(const float4*)&sX[kk*132 + ty*8 + 4];
            float2 b  = *(const float2*)&sW[kk*36 + tx*2];
            acc[0][0]+=a0.x*b.x; acc[0][1]+=a0.x*b.y;
            acc[1][0]+=a0.y*b.x; acc[1][1]+=a0.y*b.y;
            acc[2][0]+=a0.z*b.x; acc[2][1]+=a0.z*b.y;
            acc[3][0]+=a0.w*b.x; acc[3][1]+=a0.w*b.y;
            acc[4][0]+=a1.x*b.x; acc[4][1]+=a1.x*b.y;
            acc[5][0]+=a1.y*b.x; acc[5][1]+=a1.y*b.y;
            acc[6][0]+=a1.z*b.x; acc[6][1]+=a1.z*b.y;
            acc[7][0]+=a1.w*b.x; acc[7][1]+=a1.w*b.y;
        }
        __syncthreads();
        if (k1 >= K) break;
        k0 = k1;
    }

    float2 bb = *(const float2*)(bias + tx * 2);
#pragma unroll
    for (int i = 0; i < 8; i++) {
        int r = mB + ty * 8 + i;
        int b = r & (BATCH - 1);
        int t = t0 + (r >> 7);
        float2 v = make_float2(acc[i][0] + bb.x, acc[i][1] + bb.y);
        *(float2*)(out + ((size_t)b * HORIZON + t) * OBS + tx * 2) = v;
    }
}

// ---------------------------------------------------------------------------
// Phase-2 tile: 16x64, 128 thr, f32x2 inner (2m x 4n per thread).
// ---------------------------------------------------------------------------
__device__ __forceinline__ void mlp_tile(
    int mB, int nB,
    const float* __restrict__ X, int ldx, int K,
    const float* __restrict__ W, int ldw,
    const float* __restrict__ bias, bool relu,
    float* __restrict__ Y, int ldy,
    float* sX, float* sW)
{
    const int tid = threadIdx.x;
    const int ty = tid >> 4, tx = tid & 15;
    const int xr = tid >> 3, xc = tid & 7;

    const float* Xp = X + (size_t)(mB + xr) * ldx + xc * 4;
    const float* Wp = W + (size_t)(nB + xr) * ldw + xc * 4;

    float4 xv = __ldcg((const float4*)Xp);
    float4 wv[4];
#pragma unroll
    for (int j = 0; j < 4; j++)
        wv[j] = __ldg((const float4*)(Wp + (size_t)(j * 16) * ldw));

    u64 acc[2][2] = {{0ull,0ull},{0ull,0ull}};

    for (int k0 = 0;;) {
        sX[(xc*4+0)*17 + xr] = xv.x; sX[(xc*4+1)*17 + xr] = xv.y;
        sX[(xc*4+2)*17 + xr] = xv.z; sX[(xc*4+3)*17 + xr] = xv.w;
#pragma unroll
        for (int j = 0; j < 4; j++) {
            int wr = xr + j * 16;
            sW[(xc*4+0)*68 + wr] = wv[j].x; sW[(xc*4+1)*68 + wr] = wv[j].y;
            sW[(xc*4+2)*68 + wr] = wv[j].z; sW[(xc*4+3)*68 + wr] = wv[j].w;
        }
        __syncthreads();
        const int k1 = k0 + 32;
        if (k1 < K) {
            xv = __ldcg((const float4*)(Xp + k1));
#pragma unroll
            for (int j = 0; j < 4; j++)
                wv[j] = __ldg((const float4*)(Wp + (size_t)(j * 16) * ldw + k1));
        }
#pragma unroll
        for (int kk = 0; kk < 32; kk++) {
            u64 a0 = f2dup(sX[kk*17 + ty]);
            u64 a1 = f2dup(sX[kk*17 + ty + 8]);
            ulonglong2 bp = *(const ulonglong2*)&sW[kk*68 + tx*4];
            f2fma(acc[0][0], a0, bp.x); f2fma(acc[0][1], a0, bp.y);
            f2fma(acc[1][0], a1, bp.x); f2fma(acc[1][1], a1, bp.y);
        }
        __syncthreads();
        if (k1 >= K) break;
        k0 = k1;
    }

    float4 bb = make_float4(0, 0, 0, 0);
    if (bias) bb = __ldg((const float4*)(bias + nB + tx * 4));
#pragma unroll
    for (int i = 0; i < 2; i++) {
        int row = mB + ty + i * 8;
        float2 p0 = f2unpack(acc[i][0]);
        float2 p1 = f2unpack(acc[i][1]);
        float4 v = make_float4(p0.x+bb.x, p0.y+bb.y, p1.x+bb.z, p1.y+bb.w);
        if (relu) { v.x=fmaxf(v.x,0.f); v.y=fmaxf(v.y,0.f); v.z=fmaxf(v.z,0.f); v.w=fmaxf(v.w,0.f); }
        __stcg((float4*)(Y + (size_t)row * ldy + nB + tx * 4), v);
    }
}

// ---------------------------------------------------------------------------
// Phase 2: persistent AR rollout, 5 barriers/step.
//   R1..R4: Lr (128 tiles, CTAs 0..127) + Whh chunk (8 tiles, CTAs 128..135)
//   R5: per-batch-row fused L5 + output write + cell finish (CTAs 0..127)
// ---------------------------------------------------------------------------
__global__ void __launch_bounds__(128) phase2_kernel(
    const float* __restrict__ W1, const float* __restrict__ b1,
    const float* __restrict__ W2, const float* __restrict__ b2,
    const float* __restrict__ W3, const float* __restrict__ b3,
    const float* __restrict__ W4, const float* __restrict__ b4,
    const float* __restrict__ W5, const float* __restrict__ b5,
    const float* __restrict__ Wih, const float* __restrict__ Whh,
    const float* __restrict__ bih, const float* __restrict__ bhh,
    float* __restrict__ Z, float* __restrict__ A, float* __restrict__ B,
    float* __restrict__ C, float* __restrict__ out)
{
    __shared__ __align__(16) float sX[32 * 17];
    __shared__ __align__(16) float sW[32 * 68];
    unsigned target = 0;
    const int bid = blockIdx.x;
    const int tid = threadIdx.x;
    const int mT = (bid >> 4) * 16, nT = (bid & 15) * 64;

    const float* Ls[4]  = {W1, W2, W3, W4};
    const float* lb[4]  = {b1, b2, b3, b4};

    for (int t = TSTEPS; t < HORIZON; t++) {
        const float* z = Z + (size_t)t * ZSTRIDE;
        const float* lin[4] = {z, A, B, A};
        float*       lout[4] = {A, B, A, B};
        const int    lK[4]  = {LAT, HID, HID, HID};

#pragma unroll
        for (int r = 0; r < 4; r++) {
            if (bid < 128) {
                mlp_tile(mT, nT, lin[r], lK[r] == LAT ? LAT : HID, lK[r],
                         Ls[r], lK[r], lb[r], true, lout[r], HID, sX, sW);
            } else if (bid < 136) {
                int wt = r * 8 + (bid - 128);        // Whh tile 0..31
                mlp_tile((wt >> 2) * 16, (wt & 3) * 64, z, LAT, LAT,
                         Whh, LAT, (const float*)0, false, C, LAT, sX, sW);
            }
            gsync(target);
        }

        // R5: CTA b computes yh[b] = B[b,:] @ W5^T + b5, writes out, cell-finish
        if (bid < 128) {
            const int b = bid;
            // stage B row (1024 floats) into sW
            for (int i = tid; i < 256; i += 128)
                ((float4*)sW)[i] = __ldcg((const float4*)(B + (size_t)b * HID) + i);
            __syncthreads();
            // partial dot: thread (n = tid>>2, q = tid&3)
            {
                const int n = tid >> 2, q = tid & 3;
                const float4* w5 = (const float4*)(W5 + (size_t)n * HID) + q * 64;
                const float4* xb = (const float4*)sW + q * 64;
                float s = 0.f;
#pragma unroll 8
                for (int k = 0; k < 64; k++) {
                    float4 w = __ldg(w5 + k);
                    float4 x = xb[k];
                    s += x.x*w.x + x.y*w.y + x.z*w.z + x.w*w.w;
                }
                sX[tid] = s;
            }
            __syncthreads();
            if (tid < OBS) {
                float yh = sX[tid*4] + sX[tid*4+1] + sX[tid*4+2] + sX[tid*4+3]
                         + __ldg(b5 + tid);
                __stcg(out + ((size_t)b * HORIZON + t) * OBS + tid, yh);
                sX[256 + tid] = yh;
            }
            __syncthreads();
            if (t < HORIZON - 1) {
#pragma unroll
                for (int p = 0; p < 2; p++) {
                    const int n = tid + p * 128;
                    float acc = __ldcg(C + (size_t)b * LAT + n)
                              + __ldg(bih + n) + __ldg(bhh + n);
                    const float4* wr = (const float4*)(Wih + (size_t)n * OBS);
#pragma unroll
                    for (int k = 0; k < 8; k++) {
                        float4 w = __ldg(wr + k);
                        acc += sX[256+k*4+0]*w.x + sX[256+k*4+1]*w.y
                             + sX[256+k*4+2]*w.z + sX[256+k*4+3]*w.w;
                    }
                    __stcg(Z + ((size_t)t + 1) * ZSTRIDE + (size_t)b * LAT + n, tanhf(acc));
                }
            }
        }
        gsync(target);
    }
}

// ---------------------------------------------------------------------------
// Launch (13 graph nodes)
// ---------------------------------------------------------------------------
extern "C" void kernel_launch(void* const* d_in, const int* in_sizes, int n_in,
                              void* d_out, int out_size)
{
    const float* y   = (const float*)d_in[0];
    const float* Wih = (const float*)d_in[2];
    const float* Whh = (const float*)d_in[3];
    const float* bih = (const float*)d_in[4];
    const float* bhh = (const float*)d_in[5];
    const float* W1  = (const float*)d_in[6];
    const float* b1  = (const float*)d_in[7];
    const float* W2  = (const float*)d_in[8];
    const float* b2  = (const float*)d_in[9];
    const float* W3  = (const float*)d_in[10];
    const float* b3  = (const float*)d_in[11];
    const float* W4  = (const float*)d_in[12];
    const float* b4  = (const float*)d_in[13];
    const float* W5  = (const float*)d_in[14];
    const float* b5  = (const float*)d_in[15];
    float* out = (float*)d_out;

    float *Z, *A, *Bf, *C;
    unsigned* bar;
    cudaGetSymbolAddress((void**)&Z,   g_Z);
    cudaGetSymbolAddress((void**)&A,   g_A);
    cudaGetSymbolAddress((void**)&Bf,  g_B);
    cudaGetSymbolAddress((void**)&C,   g_C);
    cudaGetSymbolAddress((void**)&bar, g_bar);

    // Phase 1a
    phase1a_kernel<<<BATCH, 256>>>(y, Wih, Whh, bih, bhh, Z);

    // Phase 1b: 2 chunks of 128 steps
    const int CHUNK = 128;
    const int MBIG  = CHUNK * BATCH;   // 16384
    for (int c = 0; c < TSTEPS / CHUNK; c++) {
        const float* Xz = Z + (size_t)c * CHUNK * ZSTRIDE;
        gemm_big<1><<<dim3(HID/128, MBIG/128), 256>>>(Xz, LAT, W1, LAT, b1, A, HID, LAT);
        gemm_big<1><<<dim3(HID/128, MBIG/128), 256>>>(A, HID, W2, HID, b2, Bf, HID, HID);
        gemm_big<1><<<dim3(HID/128, MBIG/128), 256>>>(Bf, HID, W3, HID, b3, A, HID, HID);
        gemm_big<1><<<dim3(HID/128, MBIG/128), 256>>>(A, HID, W4, HID, b4, Bf, HID, HID);
        gemm_out<<<dim3(1, MBIG/128), 256>>>(Bf, HID, W5, HID, b5, out, HID, c * CHUNK);
    }

    // Phase 2
    cudaMemsetAsync(bar, 0, sizeof(unsigned));
    phase2_kernel<<<NB2, 128>>>(W1, b1, W2, b2, W3, b3, W4, b4, W5, b5,
                                Wih, Whh, bih, bhh, Z, A, Bf, C, out);
}